// round 13
// baseline (speedup 1.0000x reference)
#include <cuda_runtime.h>

#define NN 1500
#define MAXD 512
#define GO 8
#define HID 128
#define ALPHA 0.2f

typedef unsigned long long ull;

// ---------------- scratch (device globals) ---------------------------------
__device__ int2  g_cv[NN * MAXD];     // (col, val-as-int) interleaved
__device__ int   g_deg[NN];
__device__ __align__(32) float g_h[2][NN * GO];
__device__ float g_fs[2][NN];
__device__ float g_fd[2][NN];
__device__ float g_Apre[NN * HID];    // [i][k]  = w2[k]*(fc1b[k] + enc_i @ fc1w[:8,k])
__device__ float g_BpreT[HID * NN];   // [k][j]  = w2[k]*(enc_j @ fc1w[8:16,k])

// ---------------- f32x2 packed helpers (sm_103a) ---------------------------
__device__ __forceinline__ ull pk2(float lo, float hi) {
    return __double_as_longlong(__hiloint2double(__float_as_int(hi), __float_as_int(lo)));
}
__device__ __forceinline__ float lo2(ull v) {
    return __int_as_float(__double2loint(__longlong_as_double(v)));
}
__device__ __forceinline__ float hi2(ull v) {
    return __int_as_float(__double2hiint(__longlong_as_double(v)));
}
__device__ __forceinline__ ull fma2_(ull a, ull b, ull c) {
    ull d; asm("fma.rn.f32x2 %0, %1, %2, %3;" : "=l"(d) : "l"(a), "l"(b), "l"(c)); return d;
}
__device__ __forceinline__ ull add2_(ull a, ull b) {
    ull d; asm("add.rn.f32x2 %0, %1, %2;" : "=l"(d) : "l"(a), "l"(b)); return d;
}

// ---------------- CSR build + layer-1 feat (one warp per row, f4 loads) ----
__global__ void k_csr_feat(const float* __restrict__ geo, const float* __restrict__ sem,
                           const float* __restrict__ feat,
                           const float* __restrict__ W0, const float* __restrict__ a0) {
    cudaTriggerProgrammaticLaunchCompletion();
    int row  = (blockIdx.x * blockDim.x + threadIdx.x) >> 5;
    int lane = threadIdx.x & 31;
    if (row >= NN) return;

    float ev = feat[(size_t)row * 32 + lane];

    const float4* g4 = (const float4*)(geo + (size_t)row * NN);
    const float4* s4 = (const float4*)(sem + (size_t)row * NN);
    int cnt = 0;
    #pragma unroll 2
    for (int it = 0; it < 12; it++) {
        int idx = it * 32 + lane;
        bool inb = idx < 375;
        float4 gv = make_float4(0.f, 0.f, 0.f, 0.f);
        float4 sv = gv;
        if (inb) { gv = g4[idx]; sv = s4[idx]; }
        float vs[4] = {gv.x + sv.x, gv.y + sv.y, gv.z + sv.z, gv.w + sv.w};
        #pragma unroll
        for (int s = 0; s < 4; s++) {
            bool act = inb && (vs[s] > 0.f);
            unsigned m = __ballot_sync(0xffffffffu, act);
            if (act) {
                int pos = cnt + __popc(m & ((1u << lane) - 1u));
                if (pos < MAXD)
                    g_cv[row * MAXD + pos] = make_int2(idx * 4 + s, __float_as_int(vs[s]));
            }
            cnt += __popc(m);
        }
    }
    if (lane == 0) g_deg[row] = (cnt < MAXD) ? cnt : MAXD;

    float part[GO];
    #pragma unroll
    for (int o = 0; o < GO; o++) part[o] = ev * W0[lane * GO + o];
    #pragma unroll
    for (int o = 0; o < GO; o++) {
        #pragma unroll
        for (int s = 16; s > 0; s >>= 1)
            part[o] += __shfl_xor_sync(0xffffffffu, part[o], s);
    }
    if (lane < GO) g_h[0][row * GO + lane] = part[lane];
    if (lane == 0) {
        float fs = 0.f, fd = 0.f;
        #pragma unroll
        for (int o = 0; o < GO; o++) { fs += part[o] * a0[o]; fd += part[o] * a0[GO + o]; }
        g_fs[0][row] = fs;
        g_fd[0][row] = fd;
    }
}

// ---------------- gat core: single pass, 2 warps per row -------------------
__device__ __forceinline__ void gat2sp(int row, int lane, int half, int src,
                                       float* red, float enc[GO]) {
    int deg = g_deg[row];
    float fs = g_fs[src][row];

    float sum = 0.f;
    float r[GO] = {0.f, 0.f, 0.f, 0.f, 0.f, 0.f, 0.f, 0.f};
    for (int t = half * 32 + lane; t < deg; t += 64) {
        int2 cv = g_cv[row * MAXD + t];
        float v = __int_as_float(cv.y);
        float x = fs + g_fd[src][cv.x];
        x = (x >= 0.f) ? x : ALPHA * x;
        float p = __expf(x * v);
        sum += p;
        const float4* h4 = (const float4*)(g_h[src] + cv.x * GO);
        float4 h0 = h4[0], h1 = h4[1];
        r[0] += p * h0.x; r[1] += p * h0.y; r[2] += p * h0.z; r[3] += p * h0.w;
        r[4] += p * h1.x; r[5] += p * h1.y; r[6] += p * h1.z; r[7] += p * h1.w;
    }
    #pragma unroll
    for (int s = 16; s > 0; s >>= 1) {
        sum += __shfl_xor_sync(0xffffffffu, sum, s);
        #pragma unroll
        for (int q = 0; q < GO; q++) r[q] += __shfl_xor_sync(0xffffffffu, r[q], s);
    }
    if (lane == 0) {
        red[half * 9 + 0] = sum;
        #pragma unroll
        for (int q = 0; q < GO; q++) red[half * 9 + 1 + q] = r[q];
    }
    __syncthreads();

    float inv = 1.f / (red[0] + red[9]);
    #pragma unroll
    for (int o = 0; o < GO; o++) {
        float x = (red[1 + o] + red[9 + 1 + o]) * inv;
        enc[o] = (x > 0.f) ? x : (__expf(x) - 1.f);
    }
}

// ---------------- gat + next-layer feat epilogue ---------------------------
__global__ void __launch_bounds__(256) k_gat_feat(
        int src, int dst, const float* __restrict__ W, const float* __restrict__ a) {
    __shared__ float red[4][18];
    cudaTriggerProgrammaticLaunchCompletion();
    cudaGridDependencySynchronize();
    int wrp  = threadIdx.x >> 5;
    int lane = threadIdx.x & 31;
    int rloc = wrp >> 1;
    int half = wrp & 1;
    int row = blockIdx.x * 4 + rloc;

    float enc[GO];
    gat2sp(row, lane, half, src, red[rloc], enc);

    if (half == 0) {
        float h = 0.f;
        if (lane < GO) {
            #pragma unroll
            for (int c = 0; c < GO; c++) h += enc[c] * W[c * GO + lane];
            g_h[dst][row * GO + lane] = h;
        }
        float ps = (lane < GO) ? h * a[lane] : 0.f;
        float pd = (lane < GO) ? h * a[GO + lane] : 0.f;
        #pragma unroll
        for (int s = 4; s > 0; s >>= 1) {
            ps += __shfl_xor_sync(0xffffffffu, ps, s);
            pd += __shfl_xor_sync(0xffffffffu, pd, s);
        }
        if (lane == 0) { g_fs[dst][row] = ps; g_fd[dst][row] = pd; }
    }
}

// ---------------- gat + A/B precompute epilogue (w2-prescaled) -------------
__global__ void __launch_bounds__(256) k_gat_pre(
        int src, const float* __restrict__ fc1w, const float* __restrict__ fc1b,
        const float* __restrict__ fc2w) {
    __shared__ float red[4][18];
    cudaTriggerProgrammaticLaunchCompletion();
    cudaGridDependencySynchronize();
    int wrp  = threadIdx.x >> 5;
    int lane = threadIdx.x & 31;
    int rloc = wrp >> 1;
    int half = wrp & 1;
    int row = blockIdx.x * 4 + rloc;

    float enc[GO];
    gat2sp(row, lane, half, src, red[rloc], enc);

    #pragma unroll
    for (int m = 0; m < 2; m++) {
        int k = half * 32 + lane + 64 * m;
        float sa = fc1b[k], sb = 0.f;
        #pragma unroll
        for (int c = 0; c < GO; c++) {
            sa += enc[c] * fc1w[c * HID + k];
            sb += enc[c] * fc1w[(GO + c) * HID + k];
        }
        float w2k = fc2w[k];
        g_Apre[row * HID + k] = sa * w2k;
        g_BpreT[k * NN + row] = sb * w2k;
    }
}

// ---------------- pairwise MLP: 64i x 128j tile, signed-relu folding -------
// out = sum_k w2*relu(A+B+d*wd) = sum_k (w2>=0 ? max(t,0) : min(t,0)),
// t = A'' + B'' + d*wd''  with '' = w2-prescaled. FMNMX runs on alu pipe;
// accumulate is add2 (rt2) instead of fma2 (rt3).
__global__ void __launch_bounds__(256, 2) k_mlp(
        const float* __restrict__ dist,
        const float* __restrict__ fc1w,
        const float* __restrict__ fc2w,
        const float* __restrict__ fc2b,
        float* __restrict__ out) {
    __shared__ ull asp[64][32];
    __shared__ ull bll[64][33];
    __shared__ ull wz2[128];
    __shared__ unsigned smask[4];

    int i0 = blockIdx.y * 64;
    int j0 = blockIdx.x * 128;
    int tid = threadIdx.x;
    int lane = tid & 31;
    int ig = tid >> 5;
    int li = lane >> 4;
    int lj = lane & 15;
    int g  = ig * 2 + li;          // 0..15
    int ib = i0 + g * 4;           // this thread's 4 i rows

    // ---- prologue: input-only loads (overlap producers via PDL) ----
    ull dv[4][4];
    #pragma unroll
    for (int p = 0; p < 4; p++) {
        int i = ib + p;
        bool iok = i < NN;
        #pragma unroll
        for (int m = 0; m < 4; m++) {
            int j = j0 + 2 * (lj + 16 * m);
            float2 d = make_float2(0.f, 0.f);
            if (iok && j < NN) d = *(const float2*)&dist[(size_t)i * NN + j];
            dv[p][m] = pk2(d.x, d.y);
        }
    }
    if (ig < 4) {   // warps 0-3 handle k = tid (0..127)
        float w2v = fc2w[tid];
        float wdp = fc1w[2 * GO * HID + tid] * w2v;
        wz2[tid] = pk2(wdp, wdp);
        unsigned bal = __ballot_sync(0xffffffffu, w2v >= 0.f);
        if (lane == 0) smask[ig] = bal;
    }
    float bias = fc2b[0];

    cudaGridDependencySynchronize();

    ull acc[4][4];
    #pragma unroll
    for (int p = 0; p < 4; p++)
        #pragma unroll
        for (int m = 0; m < 4; m++) acc[p][m] = 0ull;

    for (int pass = 0; pass < 4; pass++) {
        int kb = pass * 32;
        __syncthreads();
        #pragma unroll
        for (int r = 0; r < 8; r++) {
            int l = tid + 256 * r;
            int kk = l & 31, ii = l >> 5;
            int gi = i0 + ii;
            float v = (gi < NN) ? g_Apre[gi * HID + kb + kk] : 0.f;
            asp[ii][kk] = pk2(v, v);
        }
        #pragma unroll
        for (int r = 0; r < 8; r++) {
            int l = tid + 256 * r;
            int jp = l & 63, kk = l >> 6;
            int j = j0 + 2 * jp;
            float2 b = make_float2(0.f, 0.f);
            if (j < NN) b = *(const float2*)&g_BpreT[(size_t)(kb + kk) * NN + j];
            bll[jp][kk] = pk2(b.x, b.y);
        }
        __syncthreads();

        unsigned mk = smask[pass];

        #pragma unroll 2
        for (int kk = 0; kk < 32; kk += 2) {
            ulonglong2 av[4];
            #pragma unroll
            for (int p = 0; p < 4; p++)
                av[p] = *(const ulonglong2*)&asp[g * 4 + p][kk];   // half-warp broadcast
            ull bk0[4], bk1[4];
            #pragma unroll
            for (int m = 0; m < 4; m++) {
                bk0[m] = bll[lj + 16 * m][kk];
                bk1[m] = bll[lj + 16 * m][kk + 1];
            }
            ull w0 = wz2[kb + kk];
            ull w1 = wz2[kb + kk + 1];
            bool p0 = (mk >> kk) & 1u;
            bool p1 = (mk >> (kk + 1)) & 1u;
            #pragma unroll
            for (int p = 0; p < 4; p++) {
                #pragma unroll
                for (int m = 0; m < 4; m++) {
                    ull t0 = fma2_(dv[p][m], w0, add2_(av[p].x, bk0[m]));
                    float l0 = p0 ? fmaxf(lo2(t0), 0.f) : fminf(lo2(t0), 0.f);
                    float h0 = p0 ? fmaxf(hi2(t0), 0.f) : fminf(hi2(t0), 0.f);
                    acc[p][m] = add2_(acc[p][m], pk2(l0, h0));
                }
            }
            #pragma unroll
            for (int p = 0; p < 4; p++) {
                #pragma unroll
                for (int m = 0; m < 4; m++) {
                    ull t1 = fma2_(dv[p][m], w1, add2_(av[p].y, bk1[m]));
                    float l1 = p1 ? fmaxf(lo2(t1), 0.f) : fminf(lo2(t1), 0.f);
                    float h1 = p1 ? fmaxf(hi2(t1), 0.f) : fminf(hi2(t1), 0.f);
                    acc[p][m] = add2_(acc[p][m], pk2(l1, h1));
                }
            }
        }
    }

    // epilogue: vectorized float2 stores
    #pragma unroll
    for (int p = 0; p < 4; p++) {
        int i = ib + p;
        if (i >= NN) continue;
        #pragma unroll
        for (int m = 0; m < 4; m++) {
            int j = j0 + 2 * (lj + 16 * m);
            if (j < NN) {
                float2 o = make_float2(lo2(acc[p][m]) + bias, hi2(acc[p][m]) + bias);
                *(float2*)&out[(size_t)i * NN + j] = o;
            }
        }
    }
}

// ---------------- launch ---------------------------------------------------
extern "C" void kernel_launch(void* const* d_in, const int* in_sizes, int n_in,
                              void* d_out, int out_size) {
    const float* geo   = (const float*)d_in[0];
    const float* sem   = (const float*)d_in[1];
    const float* feat  = (const float*)d_in[2];
    // d_in[3] region_pairs (int64) == meshgrid flattened row-major
    const float* dist  = (const float*)d_in[4];
    const float* W0    = (const float*)d_in[5];
    const float* W1    = (const float*)d_in[6];
    const float* W2    = (const float*)d_in[7];
    const float* a0    = (const float*)d_in[8];
    const float* a1    = (const float*)d_in[9];
    const float* a2    = (const float*)d_in[10];
    const float* fc1w  = (const float*)d_in[11];
    const float* fc1b  = (const float*)d_in[12];
    const float* fc2w  = (const float*)d_in[13];
    const float* fc2b  = (const float*)d_in[14];
    float* out = (float*)d_out;

    k_csr_feat<<<(NN + 7) / 8, 256>>>(geo, sem, feat, W0, a0);

    cudaLaunchAttribute attr[1];
    attr[0].id = cudaLaunchAttributeProgrammaticStreamSerialization;
    attr[0].val.programmaticStreamSerializationAllowed = 1;

    {
        cudaLaunchConfig_t cfg = {};
        cfg.gridDim = dim3(NN / 4); cfg.blockDim = dim3(256);
        cfg.attrs = attr; cfg.numAttrs = 1;
        cudaLaunchKernelEx(&cfg, k_gat_feat, 0, 1, W1, a1);
    }
    {
        cudaLaunchConfig_t cfg = {};
        cfg.gridDim = dim3(NN / 4); cfg.blockDim = dim3(256);
        cfg.attrs = attr; cfg.numAttrs = 1;
        cudaLaunchKernelEx(&cfg, k_gat_feat, 1, 0, W2, a2);
    }
    {
        cudaLaunchConfig_t cfg = {};
        cfg.gridDim = dim3(NN / 4); cfg.blockDim = dim3(256);
        cfg.attrs = attr; cfg.numAttrs = 1;
        cudaLaunchKernelEx(&cfg, k_gat_pre, 0, fc1w, fc1b, fc2w);
    }
    {
        cudaLaunchConfig_t cfg = {};
        cfg.gridDim = dim3((NN + 127) / 128, (NN + 63) / 64);
        cfg.blockDim = dim3(256);
        cfg.attrs = attr; cfg.numAttrs = 1;
        cudaLaunchKernelEx(&cfg, k_mlp, dist, fc1w, fc2w, fc2b, out);
    }
}

// round 15
// speedup vs baseline: 1.0267x; 1.0267x over previous
#include <cuda_runtime.h>

#define NN 1500
#define MAXD 512
#define GO 8
#define HID 128
#define ALPHA 0.2f

typedef unsigned long long ull;

// ---------------- scratch (device globals) ---------------------------------
__device__ int2  g_cv[NN * MAXD];     // (col, val-as-int) interleaved
__device__ int   g_deg[NN];
__device__ __align__(32) float g_h[2][NN * GO];
__device__ float g_fs[2][NN];
__device__ float g_fd[2][NN];
__device__ float g_Apre[NN * HID];    // [i][k]
__device__ float g_BpreT[HID * NN];   // [k][j]

// ---------------- f32x2 packed helpers (sm_103a) ---------------------------
__device__ __forceinline__ ull pk2(float lo, float hi) {
    return __double_as_longlong(__hiloint2double(__float_as_int(hi), __float_as_int(lo)));
}
__device__ __forceinline__ float lo2(ull v) {
    return __int_as_float(__double2loint(__longlong_as_double(v)));
}
__device__ __forceinline__ float hi2(ull v) {
    return __int_as_float(__double2hiint(__longlong_as_double(v)));
}
__device__ __forceinline__ ull fma2_(ull a, ull b, ull c) {
    ull d; asm("fma.rn.f32x2 %0, %1, %2, %3;" : "=l"(d) : "l"(a), "l"(b), "l"(c)); return d;
}
__device__ __forceinline__ ull add2_(ull a, ull b) {
    ull d; asm("add.rn.f32x2 %0, %1, %2;" : "=l"(d) : "l"(a), "l"(b)); return d;
}
// packed relu: 2 FMNMX (alu pipe, runs parallel to fma pipe) — proven best form
__device__ __forceinline__ ull relu2_(ull t) {
    return pk2(fmaxf(lo2(t), 0.f), fmaxf(hi2(t), 0.f));
}

// ---------------- CSR build + layer-1 feat (one warp per row, f4 loads) ----
__global__ void k_csr_feat(const float* __restrict__ geo, const float* __restrict__ sem,
                           const float* __restrict__ feat,
                           const float* __restrict__ W0, const float* __restrict__ a0) {
    cudaTriggerProgrammaticLaunchCompletion();
    int row  = (blockIdx.x * blockDim.x + threadIdx.x) >> 5;
    int lane = threadIdx.x & 31;
    if (row >= NN) return;

    float ev = feat[(size_t)row * 32 + lane];

    const float4* g4 = (const float4*)(geo + (size_t)row * NN);
    const float4* s4 = (const float4*)(sem + (size_t)row * NN);
    int cnt = 0;
    #pragma unroll 2
    for (int it = 0; it < 12; it++) {
        int idx = it * 32 + lane;
        bool inb = idx < 375;
        float4 gv = make_float4(0.f, 0.f, 0.f, 0.f);
        float4 sv = gv;
        if (inb) { gv = g4[idx]; sv = s4[idx]; }
        float vs[4] = {gv.x + sv.x, gv.y + sv.y, gv.z + sv.z, gv.w + sv.w};
        #pragma unroll
        for (int s = 0; s < 4; s++) {
            bool act = inb && (vs[s] > 0.f);
            unsigned m = __ballot_sync(0xffffffffu, act);
            if (act) {
                int pos = cnt + __popc(m & ((1u << lane) - 1u));
                if (pos < MAXD)
                    g_cv[row * MAXD + pos] = make_int2(idx * 4 + s, __float_as_int(vs[s]));
            }
            cnt += __popc(m);
        }
    }
    if (lane == 0) g_deg[row] = (cnt < MAXD) ? cnt : MAXD;

    float part[GO];
    #pragma unroll
    for (int o = 0; o < GO; o++) part[o] = ev * W0[lane * GO + o];
    #pragma unroll
    for (int o = 0; o < GO; o++) {
        #pragma unroll
        for (int s = 16; s > 0; s >>= 1)
            part[o] += __shfl_xor_sync(0xffffffffu, part[o], s);
    }
    if (lane < GO) g_h[0][row * GO + lane] = part[lane];
    if (lane == 0) {
        float fs = 0.f, fd = 0.f;
        #pragma unroll
        for (int o = 0; o < GO; o++) { fs += part[o] * a0[o]; fd += part[o] * a0[GO + o]; }
        g_fs[0][row] = fs;
        g_fd[0][row] = fd;
    }
}

// ---------------- gat core: single pass, 2 warps per row -------------------
__device__ __forceinline__ void gat2sp(int row, int lane, int half, int src,
                                       float* red, float enc[GO]) {
    int deg = g_deg[row];
    float fs = g_fs[src][row];

    float sum = 0.f;
    float r[GO] = {0.f, 0.f, 0.f, 0.f, 0.f, 0.f, 0.f, 0.f};
    for (int t = half * 32 + lane; t < deg; t += 64) {
        int2 cv = g_cv[row * MAXD + t];
        float v = __int_as_float(cv.y);
        float x = fs + g_fd[src][cv.x];
        x = (x >= 0.f) ? x : ALPHA * x;
        float p = __expf(x * v);
        sum += p;
        const float4* h4 = (const float4*)(g_h[src] + cv.x * GO);
        float4 h0 = h4[0], h1 = h4[1];
        r[0] += p * h0.x; r[1] += p * h0.y; r[2] += p * h0.z; r[3] += p * h0.w;
        r[4] += p * h1.x; r[5] += p * h1.y; r[6] += p * h1.z; r[7] += p * h1.w;
    }
    #pragma unroll
    for (int s = 16; s > 0; s >>= 1) {
        sum += __shfl_xor_sync(0xffffffffu, sum, s);
        #pragma unroll
        for (int q = 0; q < GO; q++) r[q] += __shfl_xor_sync(0xffffffffu, r[q], s);
    }
    if (lane == 0) {
        red[half * 9 + 0] = sum;
        #pragma unroll
        for (int q = 0; q < GO; q++) red[half * 9 + 1 + q] = r[q];
    }
    __syncthreads();

    float inv = 1.f / (red[0] + red[9]);
    #pragma unroll
    for (int o = 0; o < GO; o++) {
        float x = (red[1 + o] + red[9 + 1 + o]) * inv;
        enc[o] = (x > 0.f) ? x : (__expf(x) - 1.f);
    }
}

// ---------------- gat + next-layer feat epilogue ---------------------------
__global__ void __launch_bounds__(256) k_gat_feat(
        int src, int dst, const float* __restrict__ W, const float* __restrict__ a) {
    __shared__ float red[4][18];
    cudaTriggerProgrammaticLaunchCompletion();
    cudaGridDependencySynchronize();
    int wrp  = threadIdx.x >> 5;
    int lane = threadIdx.x & 31;
    int rloc = wrp >> 1;
    int half = wrp & 1;
    int row = blockIdx.x * 4 + rloc;

    float enc[GO];
    gat2sp(row, lane, half, src, red[rloc], enc);

    if (half == 0) {
        float h = 0.f;
        if (lane < GO) {
            #pragma unroll
            for (int c = 0; c < GO; c++) h += enc[c] * W[c * GO + lane];
            g_h[dst][row * GO + lane] = h;
        }
        float ps = (lane < GO) ? h * a[lane] : 0.f;
        float pd = (lane < GO) ? h * a[GO + lane] : 0.f;
        #pragma unroll
        for (int s = 4; s > 0; s >>= 1) {
            ps += __shfl_xor_sync(0xffffffffu, ps, s);
            pd += __shfl_xor_sync(0xffffffffu, pd, s);
        }
        if (lane == 0) { g_fs[dst][row] = ps; g_fd[dst][row] = pd; }
    }
}

// ---------------- gat + A/B precompute epilogue ----------------------------
__global__ void __launch_bounds__(256) k_gat_pre(
        int src, const float* __restrict__ fc1w, const float* __restrict__ fc1b) {
    __shared__ float red[4][18];
    cudaTriggerProgrammaticLaunchCompletion();
    cudaGridDependencySynchronize();
    int wrp  = threadIdx.x >> 5;
    int lane = threadIdx.x & 31;
    int rloc = wrp >> 1;
    int half = wrp & 1;
    int row = blockIdx.x * 4 + rloc;

    float enc[GO];
    gat2sp(row, lane, half, src, red[rloc], enc);

    #pragma unroll
    for (int m = 0; m < 2; m++) {
        int k = half * 32 + lane + 64 * m;
        float sa = fc1b[k], sb = 0.f;
        #pragma unroll
        for (int c = 0; c < GO; c++) {
            sa += enc[c] * fc1w[c * HID + k];
            sb += enc[c] * fc1w[(GO + c) * HID + k];
        }
        g_Apre[row * HID + k] = sa;
        g_BpreT[k * NN + row] = sb;
    }
}

// ---------------- pairwise MLP: 64i x 128j tile, j-packed f32x2 ------------
// 256 threads. lane = (li 0..1, lj 0..15); warp ig 0..7.
// i-group g = ig*2+li (16 groups x 4 i = 64 i). jp = lj + 16m (m 0..3) -> 64
// j-pairs = 128 j. Thread: 4 i x 4 jp = 32 elements (16 packed accs).
// bll padded to 34 ulls/row: rows 16B-aligned -> B loads as LDS.128 pairs.
__global__ void __launch_bounds__(256, 2) k_mlp(
        const float* __restrict__ dist,
        const float* __restrict__ fc1w,
        const float* __restrict__ fc2w,
        const float* __restrict__ fc2b,
        float* __restrict__ out) {
    __shared__ ull asp[64][32];
    __shared__ __align__(16) ull bll[64][34];
    __shared__ ulonglong2 wz[128];

    int i0 = blockIdx.y * 64;
    int j0 = blockIdx.x * 128;
    int tid = threadIdx.x;
    int lane = tid & 31;
    int ig = tid >> 5;
    int li = lane >> 4;
    int lj = lane & 15;
    int g  = ig * 2 + li;          // 0..15
    int ib = i0 + g * 4;           // this thread's 4 i rows

    // ---- prologue: input-only loads (overlap producers via PDL) ----
    ull dv[4][4];
    #pragma unroll
    for (int p = 0; p < 4; p++) {
        int i = ib + p;
        bool iok = i < NN;
        #pragma unroll
        for (int m = 0; m < 4; m++) {
            int j = j0 + 2 * (lj + 16 * m);
            float2 d = make_float2(0.f, 0.f);
            if (iok && j < NN) d = *(const float2*)&dist[(size_t)i * NN + j];
            dv[p][m] = pk2(d.x, d.y);
        }
    }
    if (tid < HID) {
        float wd = fc1w[2 * GO * HID + tid];
        float w2 = fc2w[tid];
        wz[tid] = make_ulonglong2(pk2(wd, wd), pk2(w2, w2));
    }
    float bias = fc2b[0];

    cudaGridDependencySynchronize();

    ull acc[4][4];
    #pragma unroll
    for (int p = 0; p < 4; p++)
        #pragma unroll
        for (int m = 0; m < 4; m++) acc[p][m] = 0ull;

    for (int pass = 0; pass < 4; pass++) {
        int kb = pass * 32;
        __syncthreads();
        #pragma unroll
        for (int r = 0; r < 8; r++) {
            int l = tid + 256 * r;
            int kk = l & 31, ii = l >> 5;
            int gi = i0 + ii;
            float v = (gi < NN) ? g_Apre[gi * HID + kb + kk] : 0.f;
            asp[ii][kk] = pk2(v, v);
        }
        #pragma unroll
        for (int r = 0; r < 8; r++) {
            int l = tid + 256 * r;
            int jp = l & 63, kk = l >> 6;
            int j = j0 + 2 * jp;
            float2 b = make_float2(0.f, 0.f);
            if (j < NN) b = *(const float2*)&g_BpreT[(size_t)(kb + kk) * NN + j];
            bll[jp][kk] = pk2(b.x, b.y);
        }
        __syncthreads();

        #pragma unroll 4
        for (int kk = 0; kk < 32; kk += 2) {
            ulonglong2 av[4];
            #pragma unroll
            for (int p = 0; p < 4; p++)
                av[p] = *(const ulonglong2*)&asp[g * 4 + p][kk];   // half-warp broadcast
            ulonglong2 bk[4];                                      // (bll[.][kk], bll[.][kk+1])
            #pragma unroll
            for (int m = 0; m < 4; m++)
                bk[m] = *(const ulonglong2*)&bll[lj + 16 * m][kk];
            ulonglong2 w0 = wz[kb + kk];
            ulonglong2 w1 = wz[kb + kk + 1];
            #pragma unroll
            for (int p = 0; p < 4; p++) {
                #pragma unroll
                for (int m = 0; m < 4; m++) {
                    ull t0 = fma2_(dv[p][m], w0.x, add2_(av[p].x, bk[m].x));
                    acc[p][m] = fma2_(relu2_(t0), w0.y, acc[p][m]);
                }
            }
            #pragma unroll
            for (int p = 0; p < 4; p++) {
                #pragma unroll
                for (int m = 0; m < 4; m++) {
                    ull t1 = fma2_(dv[p][m], w1.x, add2_(av[p].y, bk[m].y));
                    acc[p][m] = fma2_(relu2_(t1), w1.y, acc[p][m]);
                }
            }
        }
    }

    // epilogue: vectorized float2 stores (j even, NN even -> pairwise safe)
    #pragma unroll
    for (int p = 0; p < 4; p++) {
        int i = ib + p;
        if (i >= NN) continue;
        #pragma unroll
        for (int m = 0; m < 4; m++) {
            int j = j0 + 2 * (lj + 16 * m);
            if (j < NN) {
                float2 o = make_float2(lo2(acc[p][m]) + bias, hi2(acc[p][m]) + bias);
                *(float2*)&out[(size_t)i * NN + j] = o;
            }
        }
    }
}

// ---------------- launch ---------------------------------------------------
extern "C" void kernel_launch(void* const* d_in, const int* in_sizes, int n_in,
                              void* d_out, int out_size) {
    const float* geo   = (const float*)d_in[0];
    const float* sem   = (const float*)d_in[1];
    const float* feat  = (const float*)d_in[2];
    // d_in[3] region_pairs (int64) == meshgrid flattened row-major
    const float* dist  = (const float*)d_in[4];
    const float* W0    = (const float*)d_in[5];
    const float* W1    = (const float*)d_in[6];
    const float* W2    = (const float*)d_in[7];
    const float* a0    = (const float*)d_in[8];
    const float* a1    = (const float*)d_in[9];
    const float* a2    = (const float*)d_in[10];
    const float* fc1w  = (const float*)d_in[11];
    const float* fc1b  = (const float*)d_in[12];
    const float* fc2w  = (const float*)d_in[13];
    const float* fc2b  = (const float*)d_in[14];
    float* out = (float*)d_out;

    k_csr_feat<<<(NN + 7) / 8, 256>>>(geo, sem, feat, W0, a0);

    cudaLaunchAttribute attr[1];
    attr[0].id = cudaLaunchAttributeProgrammaticStreamSerialization;
    attr[0].val.programmaticStreamSerializationAllowed = 1;

    {
        cudaLaunchConfig_t cfg = {};
        cfg.gridDim = dim3(NN / 4); cfg.blockDim = dim3(256);
        cfg.attrs = attr; cfg.numAttrs = 1;
        cudaLaunchKernelEx(&cfg, k_gat_feat, 0, 1, W1, a1);
    }
    {
        cudaLaunchConfig_t cfg = {};
        cfg.gridDim = dim3(NN / 4); cfg.blockDim = dim3(256);
        cfg.attrs = attr; cfg.numAttrs = 1;
        cudaLaunchKernelEx(&cfg, k_gat_feat, 1, 0, W2, a2);
    }
    {
        cudaLaunchConfig_t cfg = {};
        cfg.gridDim = dim3(NN / 4); cfg.blockDim = dim3(256);
        cfg.attrs = attr; cfg.numAttrs = 1;
        cudaLaunchKernelEx(&cfg, k_gat_pre, 0, fc1w, fc1b);
    }
    {
        cudaLaunchConfig_t cfg = {};
        cfg.gridDim = dim3((NN + 127) / 128, (NN + 63) / 64);
        cfg.blockDim = dim3(256);
        cfg.attrs = attr; cfg.numAttrs = 1;
        cudaLaunchKernelEx(&cfg, k_mlp, dist, fc1w, fc2w, fc2b, out);
    }
}

// round 16
// speedup vs baseline: 1.1323x; 1.1028x over previous
#include <cuda_runtime.h>

#define NN 1500
#define MAXD 512
#define GO 8
#define HID 128
#define ALPHA 0.2f

typedef unsigned long long ull;

// ---------------- scratch (device globals) ---------------------------------
__device__ int2  g_cv[NN * MAXD];     // (col, val-as-int) interleaved
__device__ int   g_deg[NN];
__device__ __align__(32) float g_h[2][NN * GO];
__device__ float g_fs[2][NN];
__device__ float g_fd[2][NN];
__device__ float g_Apre[NN * HID];    // [i][k]
__device__ float g_BpreT[HID * NN];   // [k][j]

// ---------------- f32x2 packed helpers (sm_103a) ---------------------------
__device__ __forceinline__ ull pk2(float lo, float hi) {
    return __double_as_longlong(__hiloint2double(__float_as_int(hi), __float_as_int(lo)));
}
__device__ __forceinline__ float lo2(ull v) {
    return __int_as_float(__double2loint(__longlong_as_double(v)));
}
__device__ __forceinline__ float hi2(ull v) {
    return __int_as_float(__double2hiint(__longlong_as_double(v)));
}
__device__ __forceinline__ ull fma2_(ull a, ull b, ull c) {
    ull d; asm("fma.rn.f32x2 %0, %1, %2, %3;" : "=l"(d) : "l"(a), "l"(b), "l"(c)); return d;
}
__device__ __forceinline__ ull add2_(ull a, ull b) {
    ull d; asm("add.rn.f32x2 %0, %1, %2;" : "=l"(d) : "l"(a), "l"(b)); return d;
}
// packed relu: 2 FMNMX on alu pipe (parallel to fma pipe) — proven best form
__device__ __forceinline__ ull relu2_(ull t) {
    return pk2(fmaxf(lo2(t), 0.f), fmaxf(hi2(t), 0.f));
}

// ---------------- CSR build + layer-1 feat (one warp per row, f4 loads) ----
// row derived from GLOBAL warp index -> block size is a pure launch decision.
__global__ void k_csr_feat(const float* __restrict__ geo, const float* __restrict__ sem,
                           const float* __restrict__ feat,
                           const float* __restrict__ W0, const float* __restrict__ a0) {
    cudaTriggerProgrammaticLaunchCompletion();
    int row  = (blockIdx.x * blockDim.x + threadIdx.x) >> 5;
    int lane = threadIdx.x & 31;
    if (row >= NN) return;

    float ev = feat[(size_t)row * 32 + lane];

    const float4* g4 = (const float4*)(geo + (size_t)row * NN);
    const float4* s4 = (const float4*)(sem + (size_t)row * NN);
    int cnt = 0;
    #pragma unroll 2
    for (int it = 0; it < 12; it++) {
        int idx = it * 32 + lane;
        bool inb = idx < 375;
        float4 gv = make_float4(0.f, 0.f, 0.f, 0.f);
        float4 sv = gv;
        if (inb) { gv = g4[idx]; sv = s4[idx]; }
        float vs[4] = {gv.x + sv.x, gv.y + sv.y, gv.z + sv.z, gv.w + sv.w};
        #pragma unroll
        for (int s = 0; s < 4; s++) {
            bool act = inb && (vs[s] > 0.f);
            unsigned m = __ballot_sync(0xffffffffu, act);
            if (act) {
                int pos = cnt + __popc(m & ((1u << lane) - 1u));
                if (pos < MAXD)
                    g_cv[row * MAXD + pos] = make_int2(idx * 4 + s, __float_as_int(vs[s]));
            }
            cnt += __popc(m);
        }
    }
    if (lane == 0) g_deg[row] = (cnt < MAXD) ? cnt : MAXD;

    float part[GO];
    #pragma unroll
    for (int o = 0; o < GO; o++) part[o] = ev * W0[lane * GO + o];
    #pragma unroll
    for (int o = 0; o < GO; o++) {
        #pragma unroll
        for (int s = 16; s > 0; s >>= 1)
            part[o] += __shfl_xor_sync(0xffffffffu, part[o], s);
    }
    if (lane < GO) g_h[0][row * GO + lane] = part[lane];
    if (lane == 0) {
        float fs = 0.f, fd = 0.f;
        #pragma unroll
        for (int o = 0; o < GO; o++) { fs += part[o] * a0[o]; fd += part[o] * a0[GO + o]; }
        g_fs[0][row] = fs;
        g_fd[0][row] = fd;
    }
}

// ---------------- gat core: single pass, 2 warps per row -------------------
__device__ __forceinline__ void gat2sp(int row, int lane, int half, int src,
                                       float* red, float enc[GO]) {
    int deg = g_deg[row];
    float fs = g_fs[src][row];

    float sum = 0.f;
    float r[GO] = {0.f, 0.f, 0.f, 0.f, 0.f, 0.f, 0.f, 0.f};
    for (int t = half * 32 + lane; t < deg; t += 64) {
        int2 cv = g_cv[row * MAXD + t];
        float v = __int_as_float(cv.y);
        float x = fs + g_fd[src][cv.x];
        x = (x >= 0.f) ? x : ALPHA * x;
        float p = __expf(x * v);
        sum += p;
        const float4* h4 = (const float4*)(g_h[src] + cv.x * GO);
        float4 h0 = h4[0], h1 = h4[1];
        r[0] += p * h0.x; r[1] += p * h0.y; r[2] += p * h0.z; r[3] += p * h0.w;
        r[4] += p * h1.x; r[5] += p * h1.y; r[6] += p * h1.z; r[7] += p * h1.w;
    }
    #pragma unroll
    for (int s = 16; s > 0; s >>= 1) {
        sum += __shfl_xor_sync(0xffffffffu, sum, s);
        #pragma unroll
        for (int q = 0; q < GO; q++) r[q] += __shfl_xor_sync(0xffffffffu, r[q], s);
    }
    if (lane == 0) {
        red[half * 9 + 0] = sum;
        #pragma unroll
        for (int q = 0; q < GO; q++) red[half * 9 + 1 + q] = r[q];
    }
    __syncthreads();

    float inv = 1.f / (red[0] + red[9]);
    #pragma unroll
    for (int o = 0; o < GO; o++) {
        float x = (red[1 + o] + red[9 + 1 + o]) * inv;
        enc[o] = (x > 0.f) ? x : (__expf(x) - 1.f);
    }
}

// ---------------- gat + next-layer feat epilogue ---------------------------
__global__ void __launch_bounds__(256) k_gat_feat(
        int src, int dst, const float* __restrict__ W, const float* __restrict__ a) {
    __shared__ float red[4][18];
    cudaTriggerProgrammaticLaunchCompletion();
    cudaGridDependencySynchronize();
    int wrp  = threadIdx.x >> 5;
    int lane = threadIdx.x & 31;
    int rloc = wrp >> 1;
    int half = wrp & 1;
    int row = blockIdx.x * 4 + rloc;

    float enc[GO];
    gat2sp(row, lane, half, src, red[rloc], enc);

    if (half == 0) {
        float h = 0.f;
        if (lane < GO) {
            #pragma unroll
            for (int c = 0; c < GO; c++) h += enc[c] * W[c * GO + lane];
            g_h[dst][row * GO + lane] = h;
        }
        float ps = (lane < GO) ? h * a[lane] : 0.f;
        float pd = (lane < GO) ? h * a[GO + lane] : 0.f;
        #pragma unroll
        for (int s = 4; s > 0; s >>= 1) {
            ps += __shfl_xor_sync(0xffffffffu, ps, s);
            pd += __shfl_xor_sync(0xffffffffu, pd, s);
        }
        if (lane == 0) { g_fs[dst][row] = ps; g_fd[dst][row] = pd; }
    }
}

// ---------------- gat + A/B precompute epilogue ----------------------------
__global__ void __launch_bounds__(256) k_gat_pre(
        int src, const float* __restrict__ fc1w, const float* __restrict__ fc1b) {
    __shared__ float red[4][18];
    cudaTriggerProgrammaticLaunchCompletion();
    cudaGridDependencySynchronize();
    int wrp  = threadIdx.x >> 5;
    int lane = threadIdx.x & 31;
    int rloc = wrp >> 1;
    int half = wrp & 1;
    int row = blockIdx.x * 4 + rloc;

    float enc[GO];
    gat2sp(row, lane, half, src, red[rloc], enc);

    #pragma unroll
    for (int m = 0; m < 2; m++) {
        int k = half * 32 + lane + 64 * m;
        float sa = fc1b[k], sb = 0.f;
        #pragma unroll
        for (int c = 0; c < GO; c++) {
            sa += enc[c] * fc1w[c * HID + k];
            sb += enc[c] * fc1w[(GO + c) * HID + k];
        }
        g_Apre[row * HID + k] = sa;
        g_BpreT[k * NN + row] = sb;
    }
}

// ---------------- pairwise MLP: 64i x 128j tile, j-packed f32x2 ------------
// (exact R12/63.6us configuration: bll stride 33, unroll 2, split bk0/bk1)
__global__ void __launch_bounds__(256, 2) k_mlp(
        const float* __restrict__ dist,
        const float* __restrict__ fc1w,
        const float* __restrict__ fc2w,
        const float* __restrict__ fc2b,
        float* __restrict__ out) {
    __shared__ ull asp[64][32];
    __shared__ ull bll[64][33];
    __shared__ ulonglong2 wz[128];

    int i0 = blockIdx.y * 64;
    int j0 = blockIdx.x * 128;
    int tid = threadIdx.x;
    int lane = tid & 31;
    int ig = tid >> 5;
    int li = lane >> 4;
    int lj = lane & 15;
    int g  = ig * 2 + li;          // 0..15
    int ib = i0 + g * 4;           // this thread's 4 i rows

    // ---- prologue: input-only loads (overlap producers via PDL) ----
    ull dv[4][4];
    #pragma unroll
    for (int p = 0; p < 4; p++) {
        int i = ib + p;
        bool iok = i < NN;
        #pragma unroll
        for (int m = 0; m < 4; m++) {
            int j = j0 + 2 * (lj + 16 * m);
            float2 d = make_float2(0.f, 0.f);
            if (iok && j < NN) d = *(const float2*)&dist[(size_t)i * NN + j];
            dv[p][m] = pk2(d.x, d.y);
        }
    }
    if (tid < HID) {
        float wd = fc1w[2 * GO * HID + tid];
        float w2 = fc2w[tid];
        wz[tid] = make_ulonglong2(pk2(wd, wd), pk2(w2, w2));
    }
    float bias = fc2b[0];

    cudaGridDependencySynchronize();

    ull acc[4][4];
    #pragma unroll
    for (int p = 0; p < 4; p++)
        #pragma unroll
        for (int m = 0; m < 4; m++) acc[p][m] = 0ull;

    for (int pass = 0; pass < 4; pass++) {
        int kb = pass * 32;
        __syncthreads();
        #pragma unroll
        for (int r = 0; r < 8; r++) {
            int l = tid + 256 * r;
            int kk = l & 31, ii = l >> 5;
            int gi = i0 + ii;
            float v = (gi < NN) ? g_Apre[gi * HID + kb + kk] : 0.f;
            asp[ii][kk] = pk2(v, v);
        }
        #pragma unroll
        for (int r = 0; r < 8; r++) {
            int l = tid + 256 * r;
            int jp = l & 63, kk = l >> 6;
            int j = j0 + 2 * jp;
            float2 b = make_float2(0.f, 0.f);
            if (j < NN) b = *(const float2*)&g_BpreT[(size_t)(kb + kk) * NN + j];
            bll[jp][kk] = pk2(b.x, b.y);
        }
        __syncthreads();

        #pragma unroll 2
        for (int kk = 0; kk < 32; kk += 2) {
            ulonglong2 av[4];
            #pragma unroll
            for (int p = 0; p < 4; p++)
                av[p] = *(const ulonglong2*)&asp[g * 4 + p][kk];   // half-warp broadcast
            ull bk0[4], bk1[4];
            #pragma unroll
            for (int m = 0; m < 4; m++) {
                bk0[m] = bll[lj + 16 * m][kk];
                bk1[m] = bll[lj + 16 * m][kk + 1];
            }
            ulonglong2 w0 = wz[kb + kk];
            ulonglong2 w1 = wz[kb + kk + 1];
            #pragma unroll
            for (int p = 0; p < 4; p++) {
                #pragma unroll
                for (int m = 0; m < 4; m++) {
                    ull t0 = fma2_(dv[p][m], w0.x, add2_(av[p].x, bk0[m]));
                    acc[p][m] = fma2_(relu2_(t0), w0.y, acc[p][m]);
                }
            }
            #pragma unroll
            for (int p = 0; p < 4; p++) {
                #pragma unroll
                for (int m = 0; m < 4; m++) {
                    ull t1 = fma2_(dv[p][m], w1.x, add2_(av[p].y, bk1[m]));
                    acc[p][m] = fma2_(relu2_(t1), w1.y, acc[p][m]);
                }
            }
        }
    }

    // epilogue: vectorized float2 stores (j even, NN even -> pairwise safe)
    #pragma unroll
    for (int p = 0; p < 4; p++) {
        int i = ib + p;
        if (i >= NN) continue;
        #pragma unroll
        for (int m = 0; m < 4; m++) {
            int j = j0 + 2 * (lj + 16 * m);
            if (j < NN) {
                float2 o = make_float2(lo2(acc[p][m]) + bias, hi2(acc[p][m]) + bias);
                *(float2*)&out[(size_t)i * NN + j] = o;
            }
        }
    }
}

// ---------------- launch ---------------------------------------------------
extern "C" void kernel_launch(void* const* d_in, const int* in_sizes, int n_in,
                              void* d_out, int out_size) {
    const float* geo   = (const float*)d_in[0];
    const float* sem   = (const float*)d_in[1];
    const float* feat  = (const float*)d_in[2];
    // d_in[3] region_pairs (int64) == meshgrid flattened row-major
    const float* dist  = (const float*)d_in[4];
    const float* W0    = (const float*)d_in[5];
    const float* W1    = (const float*)d_in[6];
    const float* W2    = (const float*)d_in[7];
    const float* a0    = (const float*)d_in[8];
    const float* a1    = (const float*)d_in[9];
    const float* a2    = (const float*)d_in[10];
    const float* fc1w  = (const float*)d_in[11];
    const float* fc1b  = (const float*)d_in[12];
    const float* fc2w  = (const float*)d_in[13];
    const float* fc2b  = (const float*)d_in[14];
    float* out = (float*)d_out;

    // chain head: 375 blocks x 128 threads (4 warps) -> 2.53 blocks/SM,
    // balanced wave instead of 188-on-148 (1.27-wave tail).
    k_csr_feat<<<(NN + 3) / 4, 128>>>(geo, sem, feat, W0, a0);

    cudaLaunchAttribute attr[1];
    attr[0].id = cudaLaunchAttributeProgrammaticStreamSerialization;
    attr[0].val.programmaticStreamSerializationAllowed = 1;

    {
        cudaLaunchConfig_t cfg = {};
        cfg.gridDim = dim3(NN / 4); cfg.blockDim = dim3(256);
        cfg.attrs = attr; cfg.numAttrs = 1;
        cudaLaunchKernelEx(&cfg, k_gat_feat, 0, 1, W1, a1);
    }
    {
        cudaLaunchConfig_t cfg = {};
        cfg.gridDim = dim3(NN / 4); cfg.blockDim = dim3(256);
        cfg.attrs = attr; cfg.numAttrs = 1;
        cudaLaunchKernelEx(&cfg, k_gat_feat, 1, 0, W2, a2);
    }
    {
        cudaLaunchConfig_t cfg = {};
        cfg.gridDim = dim3(NN / 4); cfg.blockDim = dim3(256);
        cfg.attrs = attr; cfg.numAttrs = 1;
        cudaLaunchKernelEx(&cfg, k_gat_pre, 0, fc1w, fc1b);
    }
    {
        cudaLaunchConfig_t cfg = {};
        cfg.gridDim = dim3((NN + 127) / 128, (NN + 63) / 64);
        cfg.blockDim = dim3(256);
        cfg.attrs = attr; cfg.numAttrs = 1;
        cudaLaunchKernelEx(&cfg, k_mlp, dist, fc1w, fc2w, fc2b, out);
    }
}